// round 13
// baseline (speedup 1.0000x reference)
#include <cuda_runtime.h>
#include <cstdint>

// Problem constants (fixed by the dataset)
#define BB 4
#define NN 10000
#define EE 163840
#define NREG 2000
#define DIN 64
#define DEN 16
#define NEG_SLOPE 0.2f

// ---------------- static device scratch (no allocations allowed) -------------
__device__ float g_h[BB * NN * DEN];              // h = x @ W
__device__ float g_as[BB * NN];                   // h @ att_src
__device__ float g_ad[BB * NN];                   // h @ att_dst
__device__ float g_den[BB * NN];                  // softmax denominator per dst
__device__ __align__(16) float g_rep[BB * NN * DEN]; // unnormalized ex-weighted sums
__device__ int   g_rowstart[BB * (NREG + 1)];     // CSR row starts over sorted src
__device__ float g_ce;                            // lin_edge . att_edge (scalar)

// ---------------- K1: warp-per-node(s), W in registers -----------------------
// lane = (kslice = lane>>2, chunk = lane&3). Each lane owns W rows
// [8*kslice, 8*kslice+8) x cols [4*chunk, 4*chunk+4) in 8 float4 registers,
// amortized over a grid-stride node loop. No shared memory at all.
#define NODE_BLOCKS 296     // x 256 threads = 2368 warps (~16 warps/SM wave)

__global__ void k_node(const float* __restrict__ x, const float* __restrict__ W,
                       const float* __restrict__ att_s, const float* __restrict__ att_d,
                       const float* __restrict__ lin_edge, const float* __restrict__ att_edge) {
    if (blockIdx.x == 0 && threadIdx.x == 0) {
        float c = 0.0f;
#pragma unroll
        for (int j = 0; j < DEN; j++) c += lin_edge[j] * att_edge[j];
        g_ce = c;
    }

    int lane = threadIdx.x & 31;
    int wid = (blockIdx.x * blockDim.x + threadIdx.x) >> 5;
    int nwarps = (gridDim.x * blockDim.x) >> 5;
    int kslice = lane >> 2;       // 0..7  (8 K-values each)
    int chunk  = lane & 3;        // 0..3  (4 channels each)
    int cbase  = chunk * 4;

    // register-resident W slice: 8 rows x 4 cols
    float4 wreg[8];
#pragma unroll
    for (int r = 0; r < 8; r++)
        wreg[r] = *reinterpret_cast<const float4*>(W + (kslice * 8 + r) * DEN + cbase);

    float4 s4 = *reinterpret_cast<const float4*>(att_s + cbase);
    float4 d4 = *reinterpret_cast<const float4*>(att_d + cbase);
    const float4 z4 = make_float4(0.f, 0.f, 0.f, 0.f);

    for (int node = wid; node < BB * NN; node += nwarps) {
        // x slice for this lane: 8 floats (broadcast within each quad -> L1)
        const float4* xp = reinterpret_cast<const float4*>(x + (size_t)node * DIN + kslice * 8);
        float4 xa = xp[0], xb = xp[1];
        float xs[8] = {xa.x, xa.y, xa.z, xa.w, xb.x, xb.y, xb.z, xb.w};

        float4 acc = z4;
#pragma unroll
        for (int r = 0; r < 8; r++) {
            acc.x += xs[r] * wreg[r].x;
            acc.y += xs[r] * wreg[r].y;
            acc.z += xs[r] * wreg[r].z;
            acc.w += xs[r] * wreg[r].w;
        }

        // reduce over the 8 kslices (lanes differing in bits 2..4)
#pragma unroll
        for (int off = 4; off <= 16; off <<= 1) {
            acc.x += __shfl_xor_sync(0xFFFFFFFFu, acc.x, off);
            acc.y += __shfl_xor_sync(0xFFFFFFFFu, acc.y, off);
            acc.z += __shfl_xor_sync(0xFFFFFFFFu, acc.z, off);
            acc.w += __shfl_xor_sync(0xFFFFFFFFu, acc.w, off);
        }
        // now every lane holds the full 4-channel sums for its chunk

        float as = acc.x * s4.x + acc.y * s4.y + acc.z * s4.z + acc.w * s4.w;
        float ad = acc.x * d4.x + acc.y * d4.y + acc.z * d4.z + acc.w * d4.w;
        as += __shfl_xor_sync(0xFFFFFFFFu, as, 1);
        as += __shfl_xor_sync(0xFFFFFFFFu, as, 2);
        ad += __shfl_xor_sync(0xFFFFFFFFu, ad, 1);
        ad += __shfl_xor_sync(0xFFFFFFFFu, ad, 2);

        if (lane < 4) {   // lane == chunk for lanes 0..3
            reinterpret_cast<float4*>(g_h + (size_t)node * DEN)[lane] = acc;
            reinterpret_cast<float4*>(g_rep + (size_t)node * DEN)[lane] = z4;
        }
        if (lane == 0) {
            g_as[node] = as;
            g_ad[node] = ad;
            g_den[node] = 0.0f;
        }
    }
}

// ---------------- K2 (fused): per-edge ex; atomic den; scatter ex*h[src] -----
__device__ __forceinline__ void red_add_v4(float* p, float a, float b2, float c, float d) {
    asm volatile("red.global.add.v4.f32 [%0], {%1, %2, %3, %4};"
                 :: "l"(p), "f"(a), "f"(b2), "f"(c), "f"(d) : "memory");
}

__global__ void k_edge_fused(const int* __restrict__ ei, const float* __restrict__ ea) {
    int b = blockIdx.y;
    int e = blockIdx.x * blockDim.x + threadIdx.x;
    if (e >= EE) return;
    const int* srcp = ei + (size_t)b * 2 * EE;
    const int* dstp = srcp + EE;
    int s = srcp[e];
    int d = dstp[e];

    float v = g_as[b * NN + s] + g_ad[b * NN + d] + g_ce * ea[(size_t)b * EE + e];
    v = (v > 0.0f) ? v : NEG_SLOPE * v;
    float ex = __expf(v);

    atomicAdd(&g_den[b * NN + d], ex);

    const float4* hp = reinterpret_cast<const float4*>(g_h + (size_t)(b * NN + s) * DEN);
    float* rp = g_rep + (size_t)(b * NN + d) * DEN;
#pragma unroll
    for (int u = 0; u < DEN / 4; u++) {
        float4 h4 = hp[u];
        red_add_v4(rp + u * 4, ex * h4.x, ex * h4.y, ex * h4.z, ex * h4.w);
    }

    // CSR row starts over sorted src (every regulator guaranteed covered)
    if (e == 0) {
        g_rowstart[b * (NREG + 1) + NREG] = EE;
        g_rowstart[b * (NREG + 1) + s] = 0;
    } else if (srcp[e - 1] != s) {
        g_rowstart[b * (NREG + 1) + s] = e;
    }
}

// ---------------- K3: warp-per-regulator pool with on-the-fly normalize ------
#define POOL_WARPS 8
#define HSLOTS 256          // power of 2, >> max edges per regulator (~130)
#define DUPFLAG 0x40000000

__global__ void k_pool(const int* __restrict__ ei, const float* __restrict__ bias,
                       float* __restrict__ out) {
    __shared__ int hkey[POOL_WARPS][HSLOTS];
    __shared__ int list[POOL_WARPS][HSLOTS];
    __shared__ int lcount[POOL_WARPS];

    int warp = threadIdx.x >> 5;
    int lane = threadIdx.x & 31;
    int g = blockIdx.x * POOL_WARPS + warp;
    if (g >= BB * NREG) return;
    int b = g / NREG;
    int i = g - b * NREG;

    int s = g_rowstart[b * (NREG + 1) + i];
    int e = g_rowstart[b * (NREG + 1) + i + 1];
    int k = e - s;
    const int* dstp = ei + (size_t)b * 2 * EE + EE + s;

    // init hash
    for (int j = lane; j < HSLOTS; j += 32) hkey[warp][j] = -1;
    if (lane == 0) lcount[warp] = 0;
    __syncwarp();

    // insert all dsts; flag duplicates (rare: E[dups] ~ 0.34/regulator)
    for (int j = lane; j < k; j += 32) {
        int d = dstp[j];
        unsigned slot = ((unsigned)d * 2654435761u >> 16) & (HSLOTS - 1);
        for (int probe = 0; probe < HSLOTS; probe++) {
            int prev = atomicCAS(&hkey[warp][slot], -1, d);
            if (prev == -1) break;                         // claimed
            if ((prev & ~DUPFLAG) == d) {                  // same key -> duplicate
                if (!(prev & DUPFLAG)) atomicOr(&hkey[warp][slot], DUPFLAG);
                break;
            }
            slot = (slot + 1) & (HSLOTS - 1);
        }
    }
    __syncwarp();

    // compact singleton keys (present, not flagged)
    for (int j = lane; j < HSLOTS; j += 32) {
        int h = hkey[warp][j];
        if (h >= 0 && !(h & DUPFLAG)) {
            int p = atomicAdd(&lcount[warp], 1);
            list[warp][p] = h;
        }
    }
    __syncwarp();
    int m = lcount[warp];

    // cooperative gather with on-the-fly normalize + bias:
    // 4 lanes per rep row, each owning one float4 chunk
    int chunk = lane & 3;
    float4 bchunk = reinterpret_cast<const float4*>(bias)[chunk];
    float4 acc = make_float4(0.f, 0.f, 0.f, 0.f);
    for (int idx = lane >> 2; idx < m; idx += 8) {
        int d = list[warp][idx];
        float den = g_den[b * NN + d];
        float inv = (den > 0.0f) ? __frcp_rn(den) : 0.0f;
        const float4* rp = reinterpret_cast<const float4*>(g_rep + (size_t)(b * NN + d) * DEN);
        float4 r = rp[chunk];
        acc.x += r.x * inv + bchunk.x;
        acc.y += r.y * inv + bchunk.y;
        acc.z += r.z * inv + bchunk.z;
        acc.w += r.w * inv + bchunk.w;
    }
    // reduce across the 8 lanes sharing each chunk id (strides 16, 8, 4)
#pragma unroll
    for (int off = 16; off >= 4; off >>= 1) {
        acc.x += __shfl_down_sync(0xFFFFFFFFu, acc.x, off);
        acc.y += __shfl_down_sync(0xFFFFFFFFu, acc.y, off);
        acc.z += __shfl_down_sync(0xFFFFFFFFu, acc.z, off);
        acc.w += __shfl_down_sync(0xFFFFFFFFu, acc.w, off);
    }

    if (lane < 4) {
        // regulator i == node i; normalize its row on the fly too
        float deni = g_den[b * NN + i];
        float invi = (deni > 0.0f) ? __frcp_rn(deni) : 0.0f;
        const float4* rr = reinterpret_cast<const float4*>(g_rep + (size_t)(b * NN + i) * DEN);
        float4 rv = rr[lane];   // chunk == lane for lane<4
        rv.x = rv.x * invi + bchunk.x;
        rv.y = rv.y * invi + bchunk.y;
        rv.z = rv.z * invi + bchunk.z;
        rv.w = rv.w * invi + bchunk.w;
        float4* op = reinterpret_cast<float4*>(out + (size_t)(b * NREG + i) * DEN);
        op[lane] = make_float4(rv.x * acc.x, rv.y * acc.y, rv.z * acc.z, rv.w * acc.w);
    }
}

// ---------------- launch ------------------------------------------------------
extern "C" void kernel_launch(void* const* d_in, const int* in_sizes, int n_in,
                              void* d_out, int out_size) {
    const float* fea      = (const float*)d_in[0];   // [B,N,64]
    const int*   ei       = (const int*)d_in[1];     // [B,2,E]
    const float* ea       = (const float*)d_in[2];   // [B,E,1]
    const float* W        = (const float*)d_in[3];   // [64,16]
    const float* att_src  = (const float*)d_in[4];   // [16]
    const float* att_dst  = (const float*)d_in[5];   // [16]
    const float* lin_edge = (const float*)d_in[6];   // [1,16]
    const float* att_edge = (const float*)d_in[7];   // [16]
    const float* bias     = (const float*)d_in[8];   // [16]
    float* out = (float*)d_out;                      // [B,NREG,16]

    (void)in_sizes; (void)n_in; (void)out_size;

    k_node<<<NODE_BLOCKS, 256>>>(fea, W, att_src, att_dst, lin_edge, att_edge);
    {
        dim3 grid((EE + 255) / 256, BB);
        k_edge_fused<<<grid, 256>>>(ei, ea);
    }
    {
        int tot = BB * NREG;
        k_pool<<<(tot + POOL_WARPS - 1) / POOL_WARPS, POOL_WARPS * 32>>>(ei, bias, out);
    }
}

// round 14
// speedup vs baseline: 1.0249x; 1.0249x over previous
#include <cuda_runtime.h>
#include <cstdint>

// Problem constants (fixed by the dataset)
#define BB 4
#define NN 10000
#define EE 163840
#define NREG 2000
#define DIN 64
#define DEN 16
#define NEG_SLOPE 0.2f

// ---------------- static device scratch (no allocations allowed) -------------
__device__ float g_h[BB * NN * DEN];              // h = x @ W
__device__ float g_as[BB * NN];                   // h @ att_src
__device__ float g_ad[BB * NN];                   // h @ att_dst
__device__ float g_den[BB * NN];                  // softmax denominator per dst
__device__ __align__(16) float g_rep[BB * NN * DEN]; // unnormalized ex-weighted sums
__device__ int   g_rowstart[BB * (NREG + 1)];     // CSR row starts over sorted src
__device__ float g_ce;                            // lin_edge . att_edge (scalar)

// ---------------- K1: 4 threads/node, W in smem, x hoisted for MLP -----------
__global__ void k_node(const float* __restrict__ x, const float* __restrict__ W,
                       const float* __restrict__ att_s, const float* __restrict__ att_d,
                       const float* __restrict__ lin_edge, const float* __restrict__ att_edge) {
    __shared__ float Ws[DIN * DEN];
    for (int i = threadIdx.x; i < DIN * DEN; i += blockDim.x) Ws[i] = W[i];
    __syncthreads();

    int t = blockIdx.x * blockDim.x + threadIdx.x;
    if (t == 0) {
        float c = 0.0f;
#pragma unroll
        for (int j = 0; j < DEN; j++) c += lin_edge[j] * att_edge[j];
        g_ce = c;
    }
    if (t >= BB * NN * 4) return;
    int node = t >> 2;       // 0 .. BB*NN-1
    int chunk = t & 3;       // which float4 of the 16 output channels
    int cbase = chunk * 4;

    if (chunk == 0) g_den[node] = 0.0f;
    reinterpret_cast<float4*>(g_rep + (size_t)node * DEN)[chunk] =
        make_float4(0.f, 0.f, 0.f, 0.f);

    const float4* xr = reinterpret_cast<const float4*>(x + (size_t)node * DIN);
    float a0 = 0.f, a1 = 0.f, a2 = 0.f, a3 = 0.f;

    // ---- first half of the x row: 8 float4 hoisted (8 outstanding LDGs) ----
    float4 xv[8];
#pragma unroll
    for (int i = 0; i < 8; i++) xv[i] = xr[i];
#pragma unroll
    for (int k4 = 0; k4 < 8; k4++) {
        float4 v = xv[k4];
        const float* w0 = &Ws[(k4 * 4 + 0) * DEN + cbase];
        const float* w1 = &Ws[(k4 * 4 + 1) * DEN + cbase];
        const float* w2 = &Ws[(k4 * 4 + 2) * DEN + cbase];
        const float* w3 = &Ws[(k4 * 4 + 3) * DEN + cbase];
        a0 += v.x * w0[0] + v.y * w1[0] + v.z * w2[0] + v.w * w3[0];
        a1 += v.x * w0[1] + v.y * w1[1] + v.z * w2[1] + v.w * w3[1];
        a2 += v.x * w0[2] + v.y * w1[2] + v.z * w2[2] + v.w * w3[2];
        a3 += v.x * w0[3] + v.y * w1[3] + v.z * w2[3] + v.w * w3[3];
    }
    // ---- second half ----
#pragma unroll
    for (int i = 0; i < 8; i++) xv[i] = xr[8 + i];
#pragma unroll
    for (int k4 = 8; k4 < 16; k4++) {
        float4 v = xv[k4 - 8];
        const float* w0 = &Ws[(k4 * 4 + 0) * DEN + cbase];
        const float* w1 = &Ws[(k4 * 4 + 1) * DEN + cbase];
        const float* w2 = &Ws[(k4 * 4 + 2) * DEN + cbase];
        const float* w3 = &Ws[(k4 * 4 + 3) * DEN + cbase];
        a0 += v.x * w0[0] + v.y * w1[0] + v.z * w2[0] + v.w * w3[0];
        a1 += v.x * w0[1] + v.y * w1[1] + v.z * w2[1] + v.w * w3[1];
        a2 += v.x * w0[2] + v.y * w1[2] + v.z * w2[2] + v.w * w3[2];
        a3 += v.x * w0[3] + v.y * w1[3] + v.z * w2[3] + v.w * w3[3];
    }

    // partial attention dots over this thread's 4 channels, combined in-quad
    float as = a0 * __ldg(&att_s[cbase + 0]) + a1 * __ldg(&att_s[cbase + 1])
             + a2 * __ldg(&att_s[cbase + 2]) + a3 * __ldg(&att_s[cbase + 3]);
    float ad = a0 * __ldg(&att_d[cbase + 0]) + a1 * __ldg(&att_d[cbase + 1])
             + a2 * __ldg(&att_d[cbase + 2]) + a3 * __ldg(&att_d[cbase + 3]);
    as += __shfl_xor_sync(0xFFFFFFFFu, as, 1);
    as += __shfl_xor_sync(0xFFFFFFFFu, as, 2);
    ad += __shfl_xor_sync(0xFFFFFFFFu, ad, 1);
    ad += __shfl_xor_sync(0xFFFFFFFFu, ad, 2);

    reinterpret_cast<float4*>(g_h + (size_t)node * DEN)[chunk] =
        make_float4(a0, a1, a2, a3);
    if (chunk == 0) {
        g_as[node] = as;
        g_ad[node] = ad;
    }
}

// ---------------- K2 (fused): per-edge ex; atomic den; scatter ex*h[src] -----
__device__ __forceinline__ void red_add_v4(float* p, float a, float b2, float c, float d) {
    asm volatile("red.global.add.v4.f32 [%0], {%1, %2, %3, %4};"
                 :: "l"(p), "f"(a), "f"(b2), "f"(c), "f"(d) : "memory");
}

__global__ void k_edge_fused(const int* __restrict__ ei, const float* __restrict__ ea) {
    int b = blockIdx.y;
    int e = blockIdx.x * blockDim.x + threadIdx.x;
    if (e >= EE) return;
    const int* srcp = ei + (size_t)b * 2 * EE;
    const int* dstp = srcp + EE;
    int s = srcp[e];
    int d = dstp[e];

    float v = g_as[b * NN + s] + g_ad[b * NN + d] + g_ce * ea[(size_t)b * EE + e];
    v = (v > 0.0f) ? v : NEG_SLOPE * v;
    float ex = __expf(v);

    atomicAdd(&g_den[b * NN + d], ex);

    const float4* hp = reinterpret_cast<const float4*>(g_h + (size_t)(b * NN + s) * DEN);
    float* rp = g_rep + (size_t)(b * NN + d) * DEN;
#pragma unroll
    for (int u = 0; u < DEN / 4; u++) {
        float4 h4 = hp[u];
        red_add_v4(rp + u * 4, ex * h4.x, ex * h4.y, ex * h4.z, ex * h4.w);
    }

    // CSR row starts over sorted src (every regulator guaranteed covered)
    if (e == 0) {
        g_rowstart[b * (NREG + 1) + NREG] = EE;
        g_rowstart[b * (NREG + 1) + s] = 0;
    } else if (srcp[e - 1] != s) {
        g_rowstart[b * (NREG + 1) + s] = e;
    }
}

// ---------------- K3: warp-per-regulator pool with on-the-fly normalize ------
#define POOL_WARPS 8
#define HSLOTS 256          // power of 2, >> max edges per regulator (~130)
#define DUPFLAG 0x40000000

__global__ void k_pool(const int* __restrict__ ei, const float* __restrict__ bias,
                       float* __restrict__ out) {
    __shared__ int hkey[POOL_WARPS][HSLOTS];
    __shared__ int list[POOL_WARPS][HSLOTS];
    __shared__ int lcount[POOL_WARPS];

    int warp = threadIdx.x >> 5;
    int lane = threadIdx.x & 31;
    int g = blockIdx.x * POOL_WARPS + warp;
    if (g >= BB * NREG) return;
    int b = g / NREG;
    int i = g - b * NREG;

    int s = g_rowstart[b * (NREG + 1) + i];
    int e = g_rowstart[b * (NREG + 1) + i + 1];
    int k = e - s;
    const int* dstp = ei + (size_t)b * 2 * EE + EE + s;

    // init hash
    for (int j = lane; j < HSLOTS; j += 32) hkey[warp][j] = -1;
    if (lane == 0) lcount[warp] = 0;
    __syncwarp();

    // insert all dsts; flag duplicates (rare: E[dups] ~ 0.34/regulator)
    for (int j = lane; j < k; j += 32) {
        int d = dstp[j];
        unsigned slot = ((unsigned)d * 2654435761u >> 16) & (HSLOTS - 1);
        for (int probe = 0; probe < HSLOTS; probe++) {
            int prev = atomicCAS(&hkey[warp][slot], -1, d);
            if (prev == -1) break;                         // claimed
            if ((prev & ~DUPFLAG) == d) {                  // same key -> duplicate
                if (!(prev & DUPFLAG)) atomicOr(&hkey[warp][slot], DUPFLAG);
                break;
            }
            slot = (slot + 1) & (HSLOTS - 1);
        }
    }
    __syncwarp();

    // compact singleton keys (present, not flagged)
    for (int j = lane; j < HSLOTS; j += 32) {
        int h = hkey[warp][j];
        if (h >= 0 && !(h & DUPFLAG)) {
            int p = atomicAdd(&lcount[warp], 1);
            list[warp][p] = h;
        }
    }
    __syncwarp();
    int m = lcount[warp];

    // cooperative gather with on-the-fly normalize + bias:
    // 4 lanes per rep row, each owning one float4 chunk
    int chunk = lane & 3;
    float4 bchunk = reinterpret_cast<const float4*>(bias)[chunk];
    float4 acc = make_float4(0.f, 0.f, 0.f, 0.f);
    for (int idx = lane >> 2; idx < m; idx += 8) {
        int d = list[warp][idx];
        float den = g_den[b * NN + d];
        float inv = (den > 0.0f) ? __frcp_rn(den) : 0.0f;
        const float4* rp = reinterpret_cast<const float4*>(g_rep + (size_t)(b * NN + d) * DEN);
        float4 r = rp[chunk];
        acc.x += r.x * inv + bchunk.x;
        acc.y += r.y * inv + bchunk.y;
        acc.z += r.z * inv + bchunk.z;
        acc.w += r.w * inv + bchunk.w;
    }
    // reduce across the 8 lanes sharing each chunk id (strides 16, 8, 4)
#pragma unroll
    for (int off = 16; off >= 4; off >>= 1) {
        acc.x += __shfl_down_sync(0xFFFFFFFFu, acc.x, off);
        acc.y += __shfl_down_sync(0xFFFFFFFFu, acc.y, off);
        acc.z += __shfl_down_sync(0xFFFFFFFFu, acc.z, off);
        acc.w += __shfl_down_sync(0xFFFFFFFFu, acc.w, off);
    }

    if (lane < 4) {
        // regulator i == node i; normalize its row on the fly too
        float deni = g_den[b * NN + i];
        float invi = (deni > 0.0f) ? __frcp_rn(deni) : 0.0f;
        const float4* rr = reinterpret_cast<const float4*>(g_rep + (size_t)(b * NN + i) * DEN);
        float4 rv = rr[lane];   // chunk == lane for lane<4
        rv.x = rv.x * invi + bchunk.x;
        rv.y = rv.y * invi + bchunk.y;
        rv.z = rv.z * invi + bchunk.z;
        rv.w = rv.w * invi + bchunk.w;
        float4* op = reinterpret_cast<float4*>(out + (size_t)(b * NREG + i) * DEN);
        op[lane] = make_float4(rv.x * acc.x, rv.y * acc.y, rv.z * acc.z, rv.w * acc.w);
    }
}

// ---------------- launch ------------------------------------------------------
extern "C" void kernel_launch(void* const* d_in, const int* in_sizes, int n_in,
                              void* d_out, int out_size) {
    const float* fea      = (const float*)d_in[0];   // [B,N,64]
    const int*   ei       = (const int*)d_in[1];     // [B,2,E]
    const float* ea       = (const float*)d_in[2];   // [B,E,1]
    const float* W        = (const float*)d_in[3];   // [64,16]
    const float* att_src  = (const float*)d_in[4];   // [16]
    const float* att_dst  = (const float*)d_in[5];   // [16]
    const float* lin_edge = (const float*)d_in[6];   // [1,16]
    const float* att_edge = (const float*)d_in[7];   // [16]
    const float* bias     = (const float*)d_in[8];   // [16]
    float* out = (float*)d_out;                      // [B,NREG,16]

    (void)in_sizes; (void)n_in; (void)out_size;

    {
        int tot = BB * NN * 4;
        k_node<<<(tot + 255) / 256, 256>>>(fea, W, att_src, att_dst, lin_edge, att_edge);
    }
    {
        dim3 grid((EE + 255) / 256, BB);
        k_edge_fused<<<grid, 256>>>(ei, ea);
    }
    {
        int tot = BB * NREG;
        k_pool<<<(tot + POOL_WARPS - 1) / POOL_WARPS, POOL_WARPS * 32>>>(ei, bias, out);
    }
}

// round 15
// speedup vs baseline: 1.1745x; 1.1460x over previous
#include <cuda_runtime.h>
#include <cstdint>

// Problem constants (fixed by the dataset)
#define BB 4
#define NN 10000
#define EE 163840
#define NREG 2000
#define DIN 64
#define DEN 16
#define NEG_SLOPE 0.2f
#define CAP 64            // per-dst bin capacity (mean degree 16.4, max ~35)

// ---------------- static device scratch (no allocations allowed) -------------
__device__ float g_h[BB * NN * DEN];              // h = x @ W
__device__ float g_as[BB * NN];                   // h @ att_src
__device__ float g_ad[BB * NN];                   // h @ att_dst
__device__ int   g_cnt[BB * NN];                  // per-dst edge count (bin cursor)
__device__ __align__(16) float2 g_edata[(size_t)BB * NN * CAP]; // (ex, src) per binned edge
__device__ __align__(16) float g_rep[BB * NN * DEN]; // final rep (normalized + bias)
__device__ int   g_rowstart[BB * (NREG + 1)];     // CSR row starts over sorted src
__device__ float g_ce;                            // lin_edge . att_edge (scalar)

// ---------------- K1: 4 threads/node: h = xW, a_s, a_d; zero cnt -------------
__global__ void k_node(const float* __restrict__ x, const float* __restrict__ W,
                       const float* __restrict__ att_s, const float* __restrict__ att_d,
                       const float* __restrict__ lin_edge, const float* __restrict__ att_edge) {
    __shared__ float Ws[DIN * DEN];
    for (int i = threadIdx.x; i < DIN * DEN; i += blockDim.x) Ws[i] = W[i];
    __syncthreads();

    int t = blockIdx.x * blockDim.x + threadIdx.x;
    if (t == 0) {
        float c = 0.0f;
#pragma unroll
        for (int j = 0; j < DEN; j++) c += lin_edge[j] * att_edge[j];
        g_ce = c;
    }
    if (t >= BB * NN * 4) return;
    int node = t >> 2;       // 0 .. BB*NN-1
    int chunk = t & 3;       // which float4 of the 16 output channels
    int cbase = chunk * 4;

    if (chunk == 0) g_cnt[node] = 0;   // bin cursor for the edge pass

    const float4* xr = reinterpret_cast<const float4*>(x + (size_t)node * DIN);
    float a0 = 0.f, a1 = 0.f, a2 = 0.f, a3 = 0.f;

#pragma unroll
    for (int k4 = 0; k4 < DIN / 4; k4++) {
        float4 v = xr[k4];   // quad-lanes broadcast the same row
        const float* w0 = &Ws[(k4 * 4 + 0) * DEN + cbase];
        const float* w1 = &Ws[(k4 * 4 + 1) * DEN + cbase];
        const float* w2 = &Ws[(k4 * 4 + 2) * DEN + cbase];
        const float* w3 = &Ws[(k4 * 4 + 3) * DEN + cbase];
        a0 += v.x * w0[0] + v.y * w1[0] + v.z * w2[0] + v.w * w3[0];
        a1 += v.x * w0[1] + v.y * w1[1] + v.z * w2[1] + v.w * w3[1];
        a2 += v.x * w0[2] + v.y * w1[2] + v.z * w2[2] + v.w * w3[2];
        a3 += v.x * w0[3] + v.y * w1[3] + v.z * w2[3] + v.w * w3[3];
    }

    // partial attention dots over this thread's 4 channels, combined in-quad
    float as = a0 * __ldg(&att_s[cbase + 0]) + a1 * __ldg(&att_s[cbase + 1])
             + a2 * __ldg(&att_s[cbase + 2]) + a3 * __ldg(&att_s[cbase + 3]);
    float ad = a0 * __ldg(&att_d[cbase + 0]) + a1 * __ldg(&att_d[cbase + 1])
             + a2 * __ldg(&att_d[cbase + 2]) + a3 * __ldg(&att_d[cbase + 3]);
    as += __shfl_xor_sync(0xFFFFFFFFu, as, 1);
    as += __shfl_xor_sync(0xFFFFFFFFu, as, 2);
    ad += __shfl_xor_sync(0xFFFFFFFFu, ad, 1);
    ad += __shfl_xor_sync(0xFFFFFFFFu, ad, 2);

    reinterpret_cast<float4*>(g_h + (size_t)node * DEN)[chunk] =
        make_float4(a0, a1, a2, a3);
    if (chunk == 0) {
        g_as[node] = as;
        g_ad[node] = ad;
    }
}

// ---------------- K2: per-edge ex; bin (ex, src) by dst; row starts ----------
__global__ void k_edge_bin(const int* __restrict__ ei, const float* __restrict__ ea) {
    int b = blockIdx.y;
    int e = blockIdx.x * blockDim.x + threadIdx.x;
    if (e >= EE) return;
    const int* srcp = ei + (size_t)b * 2 * EE;
    const int* dstp = srcp + EE;
    int s = srcp[e];
    int d = dstp[e];

    float v = g_as[b * NN + s] + g_ad[b * NN + d] + g_ce * ea[(size_t)b * EE + e];
    v = (v > 0.0f) ? v : NEG_SLOPE * v;
    float ex = __expf(v);

    int node = b * NN + d;
    int pos = atomicAdd(&g_cnt[node], 1);
    if (pos < CAP)
        g_edata[(size_t)node * CAP + pos] = make_float2(ex, __int_as_float(s));

    // CSR row starts over sorted src (every regulator guaranteed covered)
    if (e == 0) {
        g_rowstart[b * (NREG + 1) + NREG] = EE;
        g_rowstart[b * (NREG + 1) + s] = 0;
    } else if (srcp[e - 1] != s) {
        g_rowstart[b * (NREG + 1) + s] = e;
    }
}

// ---------------- K3: 4 threads/node gather from bin, normalize, bias --------
__global__ void k_gather(const float* __restrict__ bias) {
    int t = blockIdx.x * blockDim.x + threadIdx.x;
    if (t >= BB * NN * 4) return;
    int node = t >> 2;
    int chunk = t & 3;
    int b = node / NN;

    int k = g_cnt[node];
    if (k > CAP) k = CAP;

    const float2* row = g_edata + (size_t)node * CAP;
    float4 acc = make_float4(0.f, 0.f, 0.f, 0.f);
    float den = 0.0f;

    for (int j = 0; j < k; j++) {
        float2 ed = row[j];                    // broadcast across the quad (L1)
        float ex = ed.x;
        int s = __float_as_int(ed.y);
        den += ex;
        float4 h4 = reinterpret_cast<const float4*>(
            g_h + (size_t)(b * NN + s) * DEN)[chunk];
        acc.x += ex * h4.x;
        acc.y += ex * h4.y;
        acc.z += ex * h4.z;
        acc.w += ex * h4.w;
    }

    float inv = (den > 0.0f) ? __frcp_rn(den) : 0.0f;
    float4 bchunk = reinterpret_cast<const float4*>(bias)[chunk];
    float4 r;
    r.x = acc.x * inv + bchunk.x;
    r.y = acc.y * inv + bchunk.y;
    r.z = acc.z * inv + bchunk.z;
    r.w = acc.w * inv + bchunk.w;
    reinterpret_cast<float4*>(g_rep + (size_t)node * DEN)[chunk] = r;
}

// ---------------- K4: warp-per-regulator hash dedup pool + output ------------
#define POOL_WARPS 8
#define HSLOTS 256          // power of 2, >> max edges per regulator (~130)
#define DUPFLAG 0x40000000

__global__ void k_pool(const int* __restrict__ ei, float* __restrict__ out) {
    __shared__ int hkey[POOL_WARPS][HSLOTS];
    __shared__ int list[POOL_WARPS][HSLOTS];
    __shared__ int lcount[POOL_WARPS];

    int warp = threadIdx.x >> 5;
    int lane = threadIdx.x & 31;
    int g = blockIdx.x * POOL_WARPS + warp;
    if (g >= BB * NREG) return;
    int b = g / NREG;
    int i = g - b * NREG;

    int s = g_rowstart[b * (NREG + 1) + i];
    int e = g_rowstart[b * (NREG + 1) + i + 1];
    int k = e - s;
    const int* dstp = ei + (size_t)b * 2 * EE + EE + s;

    // init hash
    for (int j = lane; j < HSLOTS; j += 32) hkey[warp][j] = -1;
    if (lane == 0) lcount[warp] = 0;
    __syncwarp();

    // insert all dsts; flag duplicates (rare: E[dups] ~ 0.34/regulator)
    for (int j = lane; j < k; j += 32) {
        int d = dstp[j];
        unsigned slot = ((unsigned)d * 2654435761u >> 16) & (HSLOTS - 1);
        for (int probe = 0; probe < HSLOTS; probe++) {
            int prev = atomicCAS(&hkey[warp][slot], -1, d);
            if (prev == -1) break;                         // claimed
            if ((prev & ~DUPFLAG) == d) {                  // same key -> duplicate
                if (!(prev & DUPFLAG)) atomicOr(&hkey[warp][slot], DUPFLAG);
                break;
            }
            slot = (slot + 1) & (HSLOTS - 1);
        }
    }
    __syncwarp();

    // compact singleton keys (present, not flagged)
    for (int j = lane; j < HSLOTS; j += 32) {
        int h = hkey[warp][j];
        if (h >= 0 && !(h & DUPFLAG)) {
            int p = atomicAdd(&lcount[warp], 1);
            list[warp][p] = h;
        }
    }
    __syncwarp();
    int m = lcount[warp];

    // cooperative gather: 4 lanes per rep row (one float4 chunk each)
    int chunk = lane & 3;
    float4 acc = make_float4(0.f, 0.f, 0.f, 0.f);
    for (int idx = lane >> 2; idx < m; idx += 8) {
        int d = list[warp][idx];
        const float4* rp = reinterpret_cast<const float4*>(g_rep + (size_t)(b * NN + d) * DEN);
        float4 r = rp[chunk];
        acc.x += r.x; acc.y += r.y; acc.z += r.z; acc.w += r.w;
    }
    // reduce across the 8 lanes sharing each chunk id (strides 16, 8, 4)
#pragma unroll
    for (int off = 16; off >= 4; off >>= 1) {
        acc.x += __shfl_down_sync(0xFFFFFFFFu, acc.x, off);
        acc.y += __shfl_down_sync(0xFFFFFFFFu, acc.y, off);
        acc.z += __shfl_down_sync(0xFFFFFFFFu, acc.z, off);
        acc.w += __shfl_down_sync(0xFFFFFFFFu, acc.w, off);
    }

    if (lane < 4) {
        const float4* rr = reinterpret_cast<const float4*>(g_rep + (size_t)(b * NN + i) * DEN);
        float4 rv = rr[lane];   // regulator i == node i (rep already incl. bias)
        float4* op = reinterpret_cast<float4*>(out + (size_t)(b * NREG + i) * DEN);
        op[lane] = make_float4(rv.x * acc.x, rv.y * acc.y, rv.z * acc.z, rv.w * acc.w);
    }
}

// ---------------- launch ------------------------------------------------------
extern "C" void kernel_launch(void* const* d_in, const int* in_sizes, int n_in,
                              void* d_out, int out_size) {
    const float* fea      = (const float*)d_in[0];   // [B,N,64]
    const int*   ei       = (const int*)d_in[1];     // [B,2,E]
    const float* ea       = (const float*)d_in[2];   // [B,E,1]
    const float* W        = (const float*)d_in[3];   // [64,16]
    const float* att_src  = (const float*)d_in[4];   // [16]
    const float* att_dst  = (const float*)d_in[5];   // [16]
    const float* lin_edge = (const float*)d_in[6];   // [1,16]
    const float* att_edge = (const float*)d_in[7];   // [16]
    const float* bias     = (const float*)d_in[8];   // [16]
    float* out = (float*)d_out;                      // [B,NREG,16]

    (void)in_sizes; (void)n_in; (void)out_size;

    {
        int tot = BB * NN * 4;
        k_node<<<(tot + 255) / 256, 256>>>(fea, W, att_src, att_dst, lin_edge, att_edge);
    }
    {
        dim3 grid((EE + 255) / 256, BB);
        k_edge_bin<<<grid, 256>>>(ei, ea);
    }
    {
        int tot = BB * NN * 4;
        k_gather<<<(tot + 255) / 256, 256>>>(bias);
    }
    {
        int tot = BB * NREG;
        k_pool<<<(tot + POOL_WARPS - 1) / POOL_WARPS, POOL_WARPS * 32>>>(ei, out);
    }
}

// round 16
// speedup vs baseline: 1.2192x; 1.0381x over previous
#include <cuda_runtime.h>
#include <cstdint>

// Problem constants (fixed by the dataset)
#define BB 4
#define NN 10000
#define EE 163840
#define NREG 2000
#define DIN 64
#define DEN 16
#define NEG_SLOPE 0.2f
#define CAP 64            // per-dst bin capacity (mean degree 16.4, max ~35)

// ---------------- static device scratch (no allocations allowed) -------------
__device__ float g_h[BB * NN * DEN];              // h = x @ W
__device__ float g_as[BB * NN];                   // h @ att_src
__device__ float g_ad[BB * NN];                   // h @ att_dst
__device__ int   g_cnt[BB * NN];                  // per-dst edge count (bin cursor)
__device__ __align__(16) float2 g_edata[(size_t)BB * NN * CAP]; // (ex, src) per binned edge
__device__ __align__(16) float g_rep[BB * NN * DEN]; // final rep (normalized + bias)
__device__ int   g_rowstart[BB * (NREG + 1)];     // CSR row starts over sorted src
__device__ float g_ce;                            // lin_edge . att_edge (scalar)

// ---------------- K1: shared-x staging, 4 threads/node -----------------------
// Block = 256 threads = 64 nodes. Stage the 64 x rows (16 KB) into padded
// shared memory with fully-coalesced MLP=4 loads, then compute h from LDS.
#define NODES_PER_BLK 64
#define XSTRIDE 68        // 64 + 4 pad floats: 272 B row stride -> conflict-free

__global__ void k_node(const float* __restrict__ x, const float* __restrict__ W,
                       const float* __restrict__ att_s, const float* __restrict__ att_d,
                       const float* __restrict__ lin_edge, const float* __restrict__ att_edge) {
    __shared__ float Ws[DIN * DEN];                    // 4 KB
    __shared__ float Xs[NODES_PER_BLK * XSTRIDE];      // 17.4 KB

    int tid = threadIdx.x;
    for (int i = tid; i < DIN * DEN; i += 256) Ws[i] = W[i];

    if (blockIdx.x == 0 && tid == 0) {
        float c = 0.0f;
#pragma unroll
        for (int j = 0; j < DEN; j++) c += lin_edge[j] * att_edge[j];
        g_ce = c;
    }

    // stage 64 rows x 64 floats = 1024 float4, coalesced, 4 independent LDGs/thread
    int base = blockIdx.x * NODES_PER_BLK;             // first node of this block
    const float4* xg = reinterpret_cast<const float4*>(x + (size_t)base * DIN);
#pragma unroll
    for (int i = 0; i < 4; i++) {
        int idx = tid + i * 256;       // float4 index 0..1023
        int row = idx >> 4;            // 16 float4 per row
        int col = idx & 15;
        *reinterpret_cast<float4*>(&Xs[row * XSTRIDE + col * 4]) = xg[idx];
    }
    __syncthreads();

    int node = base + (tid >> 2);      // 40000 = 625*64, always in range
    int chunk = tid & 3;
    int cbase = chunk * 4;

    if (chunk == 0) g_cnt[node] = 0;   // bin cursor for the edge pass

    const float* xrow = &Xs[(tid >> 2) * XSTRIDE];
    float a0 = 0.f, a1 = 0.f, a2 = 0.f, a3 = 0.f;

#pragma unroll
    for (int k4 = 0; k4 < DIN / 4; k4++) {
        float4 v = *reinterpret_cast<const float4*>(&xrow[k4 * 4]);  // LDS broadcast
        const float* w0 = &Ws[(k4 * 4 + 0) * DEN + cbase];
        const float* w1 = &Ws[(k4 * 4 + 1) * DEN + cbase];
        const float* w2 = &Ws[(k4 * 4 + 2) * DEN + cbase];
        const float* w3 = &Ws[(k4 * 4 + 3) * DEN + cbase];
        a0 += v.x * w0[0] + v.y * w1[0] + v.z * w2[0] + v.w * w3[0];
        a1 += v.x * w0[1] + v.y * w1[1] + v.z * w2[1] + v.w * w3[1];
        a2 += v.x * w0[2] + v.y * w1[2] + v.z * w2[2] + v.w * w3[2];
        a3 += v.x * w0[3] + v.y * w1[3] + v.z * w2[3] + v.w * w3[3];
    }

    // partial attention dots over this thread's 4 channels, combined in-quad
    float as = a0 * __ldg(&att_s[cbase + 0]) + a1 * __ldg(&att_s[cbase + 1])
             + a2 * __ldg(&att_s[cbase + 2]) + a3 * __ldg(&att_s[cbase + 3]);
    float ad = a0 * __ldg(&att_d[cbase + 0]) + a1 * __ldg(&att_d[cbase + 1])
             + a2 * __ldg(&att_d[cbase + 2]) + a3 * __ldg(&att_d[cbase + 3]);
    as += __shfl_xor_sync(0xFFFFFFFFu, as, 1);
    as += __shfl_xor_sync(0xFFFFFFFFu, as, 2);
    ad += __shfl_xor_sync(0xFFFFFFFFu, ad, 1);
    ad += __shfl_xor_sync(0xFFFFFFFFu, ad, 2);

    reinterpret_cast<float4*>(g_h + (size_t)node * DEN)[chunk] =
        make_float4(a0, a1, a2, a3);
    if (chunk == 0) {
        g_as[node] = as;
        g_ad[node] = ad;
    }
}

// ---------------- K2: per-edge ex; bin (ex, src) by dst; row starts ----------
__global__ void k_edge_bin(const int* __restrict__ ei, const float* __restrict__ ea) {
    int b = blockIdx.y;
    int e = blockIdx.x * blockDim.x + threadIdx.x;
    if (e >= EE) return;
    const int* srcp = ei + (size_t)b * 2 * EE;
    const int* dstp = srcp + EE;
    int s = srcp[e];
    int d = dstp[e];

    float v = g_as[b * NN + s] + g_ad[b * NN + d] + g_ce * ea[(size_t)b * EE + e];
    v = (v > 0.0f) ? v : NEG_SLOPE * v;
    float ex = __expf(v);

    int node = b * NN + d;
    int pos = atomicAdd(&g_cnt[node], 1);
    if (pos < CAP)
        g_edata[(size_t)node * CAP + pos] = make_float2(ex, __int_as_float(s));

    // CSR row starts over sorted src (every regulator guaranteed covered)
    if (e == 0) {
        g_rowstart[b * (NREG + 1) + NREG] = EE;
        g_rowstart[b * (NREG + 1) + s] = 0;
    } else if (srcp[e - 1] != s) {
        g_rowstart[b * (NREG + 1) + s] = e;
    }
}

// ---------------- K3: 4 threads/node gather from bin, normalize, bias --------
__global__ void k_gather(const float* __restrict__ bias) {
    int t = blockIdx.x * blockDim.x + threadIdx.x;
    if (t >= BB * NN * 4) return;
    int node = t >> 2;
    int chunk = t & 3;
    int b = node / NN;

    int k = g_cnt[node];
    if (k > CAP) k = CAP;

    const float2* row = g_edata + (size_t)node * CAP;
    float4 acc = make_float4(0.f, 0.f, 0.f, 0.f);
    float den = 0.0f;

    for (int j = 0; j < k; j++) {
        float2 ed = row[j];                    // broadcast across the quad (L1)
        float ex = ed.x;
        int s = __float_as_int(ed.y);
        den += ex;
        float4 h4 = reinterpret_cast<const float4*>(
            g_h + (size_t)(b * NN + s) * DEN)[chunk];
        acc.x += ex * h4.x;
        acc.y += ex * h4.y;
        acc.z += ex * h4.z;
        acc.w += ex * h4.w;
    }

    float inv = (den > 0.0f) ? __frcp_rn(den) : 0.0f;
    float4 bchunk = reinterpret_cast<const float4*>(bias)[chunk];
    float4 r;
    r.x = acc.x * inv + bchunk.x;
    r.y = acc.y * inv + bchunk.y;
    r.z = acc.z * inv + bchunk.z;
    r.w = acc.w * inv + bchunk.w;
    reinterpret_cast<float4*>(g_rep + (size_t)node * DEN)[chunk] = r;
}

// ---------------- K4: warp-per-regulator hash dedup pool + output ------------
#define POOL_WARPS 8
#define HSLOTS 256          // power of 2, >> max edges per regulator (~130)
#define DUPFLAG 0x40000000

__global__ void k_pool(const int* __restrict__ ei, float* __restrict__ out) {
    __shared__ int hkey[POOL_WARPS][HSLOTS];
    __shared__ int list[POOL_WARPS][HSLOTS];
    __shared__ int lcount[POOL_WARPS];

    int warp = threadIdx.x >> 5;
    int lane = threadIdx.x & 31;
    int g = blockIdx.x * POOL_WARPS + warp;
    if (g >= BB * NREG) return;
    int b = g / NREG;
    int i = g - b * NREG;

    int s = g_rowstart[b * (NREG + 1) + i];
    int e = g_rowstart[b * (NREG + 1) + i + 1];
    int k = e - s;
    const int* dstp = ei + (size_t)b * 2 * EE + EE + s;

    // init hash
    for (int j = lane; j < HSLOTS; j += 32) hkey[warp][j] = -1;
    if (lane == 0) lcount[warp] = 0;
    __syncwarp();

    // insert all dsts; flag duplicates (rare: E[dups] ~ 0.34/regulator)
    for (int j = lane; j < k; j += 32) {
        int d = dstp[j];
        unsigned slot = ((unsigned)d * 2654435761u >> 16) & (HSLOTS - 1);
        for (int probe = 0; probe < HSLOTS; probe++) {
            int prev = atomicCAS(&hkey[warp][slot], -1, d);
            if (prev == -1) break;                         // claimed
            if ((prev & ~DUPFLAG) == d) {                  // same key -> duplicate
                if (!(prev & DUPFLAG)) atomicOr(&hkey[warp][slot], DUPFLAG);
                break;
            }
            slot = (slot + 1) & (HSLOTS - 1);
        }
    }
    __syncwarp();

    // compact singleton keys (present, not flagged)
    for (int j = lane; j < HSLOTS; j += 32) {
        int h = hkey[warp][j];
        if (h >= 0 && !(h & DUPFLAG)) {
            int p = atomicAdd(&lcount[warp], 1);
            list[warp][p] = h;
        }
    }
    __syncwarp();
    int m = lcount[warp];

    // cooperative gather: 4 lanes per rep row (one float4 chunk each)
    int chunk = lane & 3;
    float4 acc = make_float4(0.f, 0.f, 0.f, 0.f);
    for (int idx = lane >> 2; idx < m; idx += 8) {
        int d = list[warp][idx];
        const float4* rp = reinterpret_cast<const float4*>(g_rep + (size_t)(b * NN + d) * DEN);
        float4 r = rp[chunk];
        acc.x += r.x; acc.y += r.y; acc.z += r.z; acc.w += r.w;
    }
    // reduce across the 8 lanes sharing each chunk id (strides 16, 8, 4)
#pragma unroll
    for (int off = 16; off >= 4; off >>= 1) {
        acc.x += __shfl_down_sync(0xFFFFFFFFu, acc.x, off);
        acc.y += __shfl_down_sync(0xFFFFFFFFu, acc.y, off);
        acc.z += __shfl_down_sync(0xFFFFFFFFu, acc.z, off);
        acc.w += __shfl_down_sync(0xFFFFFFFFu, acc.w, off);
    }

    if (lane < 4) {
        const float4* rr = reinterpret_cast<const float4*>(g_rep + (size_t)(b * NN + i) * DEN);
        float4 rv = rr[lane];   // regulator i == node i (rep already incl. bias)
        float4* op = reinterpret_cast<float4*>(out + (size_t)(b * NREG + i) * DEN);
        op[lane] = make_float4(rv.x * acc.x, rv.y * acc.y, rv.z * acc.z, rv.w * acc.w);
    }
}

// ---------------- launch ------------------------------------------------------
extern "C" void kernel_launch(void* const* d_in, const int* in_sizes, int n_in,
                              void* d_out, int out_size) {
    const float* fea      = (const float*)d_in[0];   // [B,N,64]
    const int*   ei       = (const int*)d_in[1];     // [B,2,E]
    const float* ea       = (const float*)d_in[2];   // [B,E,1]
    const float* W        = (const float*)d_in[3];   // [64,16]
    const float* att_src  = (const float*)d_in[4];   // [16]
    const float* att_dst  = (const float*)d_in[5];   // [16]
    const float* lin_edge = (const float*)d_in[6];   // [1,16]
    const float* att_edge = (const float*)d_in[7];   // [16]
    const float* bias     = (const float*)d_in[8];   // [16]
    float* out = (float*)d_out;                      // [B,NREG,16]

    (void)in_sizes; (void)n_in; (void)out_size;

    {
        int nblk = (BB * NN) / NODES_PER_BLK;   // 625
        k_node<<<nblk, 256>>>(fea, W, att_src, att_dst, lin_edge, att_edge);
    }
    {
        dim3 grid((EE + 255) / 256, BB);
        k_edge_bin<<<grid, 256>>>(ei, ea);
    }
    {
        int tot = BB * NN * 4;
        k_gather<<<(tot + 255) / 256, 256>>>(bias);
    }
    {
        int tot = BB * NREG;
        k_pool<<<(tot + POOL_WARPS - 1) / POOL_WARPS, POOL_WARPS * 32>>>(ei, out);
    }
}